// round 15
// baseline (speedup 1.0000x reference)
#include <cuda_runtime.h>
#include <cuda_fp16.h>
#include <cstdint>

#define N_NODES 100000
#define EDGES   640000
#define LAYERS  5
#define BN_EPS  1e-5f
#define NT      1563         // ceil(100000/64): M-tile 64 for both GEMMs
#define GRID_G  148
#define NSCAN   98

// ---------------- static scratch ------------------------------------------------
__device__ __half g_a_hi[(size_t)N_NODES * 128];
__device__ __half g_a_lo[(size_t)N_NODES * 128];
__device__ __half g_z_hi[(size_t)N_NODES * 256];
__device__ __half g_z_lo[(size_t)N_NODES * 256];
__device__ __half g_w1t[LAYERS * 32768];   // [l][n=256][k=128], single fp16 plane
__device__ __half g_w2t[LAYERS * 32768];   // [l][n=128][k=256], single fp16 plane
__device__ int g_rowptr[N_NODES + 1];
__device__ int g_cnt[N_NODES];
__device__ int g_cursor[N_NODES];
__device__ int g_srcs[EDGES];
__device__ int g_pre[NSCAN];
__device__ int g_flag[NSCAN];

// ---------------- helpers -------------------------------------------------------
__device__ __forceinline__ uint32_t smem_u32(const void* p) {
    uint32_t a;
    asm("{ .reg .u64 t; cvta.to.shared.u64 t, %1; cvt.u32.u64 %0, t; }" : "=r"(a) : "l"(p));
    return a;
}
__device__ __forceinline__ uint32_t pack_h(__half a, __half b) {
    return ((uint32_t)__half_as_ushort(b) << 16) | (uint32_t)__half_as_ushort(a);
}
__device__ __forceinline__ void split_h(float x, __half& h, __half& l) {
    h = __float2half(x);
    l = __float2half(x - __half2float(h));
}

#define LDSM_X4(r0, r1, r2, r3, addr) \
    asm volatile("ldmatrix.sync.aligned.m8n8.x4.shared.b16 {%0,%1,%2,%3}, [%4];" \
        : "=r"(r0), "=r"(r1), "=r"(r2), "=r"(r3) : "r"(addr))

__device__ __forceinline__ void mma_h32(float& c0, float& c1, float& c2, float& c3,
        uint32_t a0, uint32_t a1, uint32_t a2, uint32_t a3, uint32_t b0, uint32_t b1) {
    asm volatile("mma.sync.aligned.m16n8k16.row.col.f32.f16.f16.f32 "
        "{%0,%1,%2,%3}, {%4,%5,%6,%7}, {%8,%9}, {%0,%1,%2,%3};"
        : "+f"(c0), "+f"(c1), "+f"(c2), "+f"(c3)
        : "r"(a0), "r"(a1), "r"(a2), "r"(a3), "r"(b0), "r"(b1));
}

__device__ __forceinline__ void cp16(uint32_t dst, const void* src, uint32_t srcsz) {
    asm volatile("cp.async.ca.shared.global [%0], [%1], 16, %2;"
                 :: "r"(dst), "l"(src), "r"(srcsz) : "memory");
}
#define CP_COMMIT() asm volatile("cp.async.commit_group;" ::: "memory")
#define CP_WAIT0()  asm volatile("cp.async.wait_group 0;" ::: "memory")

// ---------------- prep: W fp16 transpose + CSR/flag zero (fused) -----------------
__global__ void k_prep(const float* __restrict__ W1, const float* __restrict__ W2) {
    int i = blockIdx.x * blockDim.x + threadIdx.x;
    const int TOT = LAYERS * 32768;
    if (i < N_NODES) { g_cnt[i] = 0; g_cursor[i] = 0; }
    if (i < NSCAN) g_flag[i] = 0;
    if (i < TOT) {
        int l = i >> 15, r = i & 32767;
        int k = r >> 8, n = r & 255;           // W1[l][k][n]
        g_w1t[(size_t)l * 32768 + n * 128 + k] = __float2half(W1[i]);
    } else if (i < 2 * TOT) {
        int j = i - TOT;
        int l = j >> 15, r = j & 32767;
        int k = r >> 7, n = r & 127;           // W2[l][k][n]
        g_w2t[(size_t)l * 32768 + n * 256 + k] = __float2half(W2[j]);
    }
}

// ---------------- CSR build ------------------------------------------------------
__global__ void k_hist(const int* __restrict__ dst) {
    int e = blockIdx.x * blockDim.x + threadIdx.x;
    if (e < EDGES) atomicAdd(&g_cnt[dst[e]], 1);
}
// single-pass chained scan: 98 blocks, all co-resident (98 <= 148 SMs)
__global__ void k_scan() {
    __shared__ int s[1024];
    __shared__ int prefix;
    int t = threadIdx.x, b = blockIdx.x;
    int i = b * 1024 + t;
    int v = (i < N_NODES) ? g_cnt[i] : 0;
    s[t] = v;
    __syncthreads();
    #pragma unroll
    for (int off = 1; off < 1024; off <<= 1) {
        int u = (t >= off) ? s[t - off] : 0;
        __syncthreads();
        s[t] += u;
        __syncthreads();
    }
    if (t == 0) {
        if (b == 0) prefix = 0;
        else {
            while (atomicAdd(&g_flag[b - 1], 0) == 0) {}
            prefix = g_pre[b - 1];
        }
    }
    __syncthreads();
    if (t == 1023) {
        g_pre[b] = prefix + s[1023];
        __threadfence();
        atomicExch(&g_flag[b], 1);
    }
    if (i < N_NODES) g_rowptr[i + 1] = prefix + s[t];
    if (i == 0) g_rowptr[0] = 0;
}
__global__ void k_fill(const int* __restrict__ src, const int* __restrict__ dst) {
    int e = blockIdx.x * blockDim.x + threadIdx.x;
    if (e < EDGES) {
        int d = dst[e];
        int p = g_rowptr[d] + atomicAdd(&g_cursor[d], 1);
        g_srcs[p] = src[e];
    }
}

// ---------------- aggregation: agg = h_i + sum h_j -> split fp16 -----------------
__global__ void k_aggregate(const float* __restrict__ h) {
    int gw = (blockIdx.x * blockDim.x + threadIdx.x) >> 5;
    int lane = threadIdx.x & 31;
    if (gw >= N_NODES) return;
    const float4* hv = (const float4*)h;
    float4 acc = __ldg(&hv[(size_t)gw * 32 + lane]);
    int e0 = g_rowptr[gw], e1 = g_rowptr[gw + 1];
    for (int e = e0; e < e1; e++) {
        int j = g_srcs[e];
        float4 v = __ldg(&hv[(size_t)j * 32 + lane]);
        acc.x += v.x; acc.y += v.y; acc.z += v.z; acc.w += v.w;
    }
    __half h0, h1, h2, h3, l0, l1, l2, l3;
    split_h(acc.x, h0, l0); split_h(acc.y, h1, l1);
    split_h(acc.z, h2, l2); split_h(acc.w, h3, l3);
    uint2 ph, pl;
    ph.x = pack_h(h0, h1); ph.y = pack_h(h2, h3);
    pl.x = pack_h(l0, l1); pl.y = pack_h(l2, l3);
    ((uint2*)g_a_hi)[(size_t)gw * 32 + lane] = ph;
    ((uint2*)g_a_lo)[(size_t)gw * 32 + lane] = pl;
}

// ---------------- SMEM layouts ----------------------------------------------------
// GEMM1: alpha|beta | W [256][272] | A double buf [2][hi/lo][64][272]
#define STR1B    272
#define G1_ALPHA 0
#define G1_BETA  1024
#define G1_W     2048
#define G1_A     71680
#define G1_BUF   34816
#define G1_LO    17408
#define SMEM1    141312
// GEMM2: W [128][528] | chunk double buf [2][hi/lo][64][272] | alpha|beta
#define STR2B    528
#define G2_W     0
#define G2_Z     67584
#define G2_BUF   34816
#define G2_LO    17408
#define G2_ALPHA 137216
#define G2_BETA  137728
#define SMEM2    138240

// ---- cp.async full-tile issuers: one commit group per issue ---------------------
__device__ __forceinline__ void g1_issue(uint32_t sb, int tid, int row0, int buf) {
    int hl = tid >> 8;
    int t = tid & 255;
    int r = t >> 2, c = t & 3;
    int gr = row0 + r;
    uint32_t p = (gr < N_NODES) ? 16u : 0u;
    const char* gsrc = (const char*)(hl ? g_a_lo : g_a_hi) + (size_t)gr * 256 + c * 16;
    uint32_t dsm = sb + G1_A + buf * G1_BUF + hl * G1_LO + r * STR1B + c * 16;
    #pragma unroll
    for (int g = 0; g < 4; g++) cp16(dsm + g * 64, gsrc + g * 64, p);
    CP_COMMIT();
}
__device__ __forceinline__ void g2_issue(uint32_t sb, int tid, int row0, int ch, int buf) {
    int hl = tid >> 8;
    int t = tid & 255;
    int r = t >> 2, c = t & 3;
    int gr = row0 + r;
    uint32_t p = (gr < N_NODES) ? 16u : 0u;
    const char* gsrc = (const char*)(hl ? g_z_lo : g_z_hi) + (size_t)gr * 512 + ch * 256 + c * 16;
    uint32_t dsm = sb + G2_Z + buf * G2_BUF + hl * G2_LO + r * STR1B + c * 16;
    #pragma unroll
    for (int g = 0; g < 4; g++) cp16(dsm + g * 64, gsrc + g * 64, p);
    CP_COMMIT();
}

// ---------------- GEMM1: z = relu(BN1(agg @ W1 + b1)),  [N,128]x[128,256] --------
// 512 thr, 16 warps: 2m x 8n, warp tile m32 x n32; M-tile 64; double-buffered A
// 2-term: (Ah + Al) x W16, 16 MMAs/kstep
__global__ void __launch_bounds__(512, 1) k_gemm1(
    int layer, const float* __restrict__ bias,
    const float* __restrict__ bn_g, const float* __restrict__ bn_b,
    const float* __restrict__ bn_m, const float* __restrict__ bn_v)
{
    extern __shared__ char sm[];
    uint32_t sb = smem_u32(sm);
    int tid = threadIdx.x, lane = tid & 31, wid = tid >> 5;

    g1_issue(sb, tid, blockIdx.x << 6, 0);   // prefetch first tile into buf0

    {   // W into padded smem [n=256][k=128]
        const uint4* s = (const uint4*)(g_w1t + (size_t)layer * 32768);
        #pragma unroll 2
        for (int i = tid; i < 4096; i += 512) {
            int r = i >> 4, c = i & 15;
            *(uint4*)(sm + G1_W + r * STR1B + c * 16) = s[i];
        }
    }
    float* sAl = (float*)(sm + G1_ALPHA);
    float* sBe = (float*)(sm + G1_BETA);
    if (tid < 256) {
        float s = bn_g[tid] * rsqrtf(bn_v[tid] + BN_EPS);
        sAl[tid] = s;
        sBe[tid] = (bias[tid] - bn_m[tid]) * s + bn_b[tid];
    }
    __syncthreads();

    int m0 = (wid >> 3) * 32, n0 = (wid & 7) * 32;
    uint32_t aoffA = (uint32_t)((m0 + (lane & 15)) * STR1B + ((lane >> 4) << 4));
    uint32_t boff = (uint32_t)((n0 + ((lane >> 4) << 3) + (lane & 7)) * STR1B + (((lane >> 3) & 1) << 4));
    uint32_t aW = sb + G1_W + boff;
    int q = lane & 3;

    int buf = 0;
    for (int tile = blockIdx.x; tile < NT; tile += gridDim.x) {
        int row0 = tile << 6;
        CP_WAIT0();            // current buffer ready
        __syncthreads();       // all warps past previous tile's reads
        g1_issue(sb, tid, (tile + gridDim.x) << 6, buf ^ 1);   // prefetch next

        uint32_t aAH = sb + G1_A + buf * G1_BUF + aoffA;
        uint32_t aAL = aAH + G1_LO;

        float acc[2][4][4];
        #pragma unroll
        for (int i = 0; i < 2; i++)
            #pragma unroll
            for (int j = 0; j < 4; j++)
                #pragma unroll
                for (int f = 0; f < 4; f++) acc[i][j][f] = 0.f;

        #pragma unroll 2
        for (int ks = 0; ks < 8; ks++) {
            uint32_t kb = (uint32_t)ks << 5;
            uint32_t Ah[2][4], Alr[2][4], B[4];
            #pragma unroll
            for (int i = 0; i < 2; i++) {
                LDSM_X4(Ah[i][0], Ah[i][1], Ah[i][2], Ah[i][3], aAH + i * (16 * STR1B) + kb);
                LDSM_X4(Alr[i][0], Alr[i][1], Alr[i][2], Alr[i][3], aAL + i * (16 * STR1B) + kb);
            }
            #pragma unroll
            for (int j2 = 0; j2 < 2; j2++) {
                LDSM_X4(B[0], B[1], B[2], B[3], aW + j2 * (16 * STR1B) + kb);
                #pragma unroll
                for (int i = 0; i < 2; i++)
                    #pragma unroll
                    for (int jj = 0; jj < 2; jj++)
                        mma_h32(acc[i][j2*2+jj][0], acc[i][j2*2+jj][1],
                                acc[i][j2*2+jj][2], acc[i][j2*2+jj][3],
                                Ah[i][0], Ah[i][1], Ah[i][2], Ah[i][3],
                                B[jj*2], B[jj*2+1]);
                #pragma unroll
                for (int i = 0; i < 2; i++)
                    #pragma unroll
                    for (int jj = 0; jj < 2; jj++)
                        mma_h32(acc[i][j2*2+jj][0], acc[i][j2*2+jj][1],
                                acc[i][j2*2+jj][2], acc[i][j2*2+jj][3],
                                Alr[i][0], Alr[i][1], Alr[i][2], Alr[i][3],
                                B[jj*2], B[jj*2+1]);
            }
        }

        // epilogue: BN + relu + split-fp16 store of z (overlaps inflight prefetch)
        uint32_t* zh = (uint32_t*)g_z_hi;
        uint32_t* zl = (uint32_t*)g_z_lo;
        #pragma unroll
        for (int i = 0; i < 2; i++) {
            #pragma unroll
            for (int hf = 0; hf < 2; hf++) {
                int r = row0 + m0 + i * 16 + (lane >> 2) + hf * 8;
                if (r < N_NODES) {
                    size_t rb = (size_t)r * 128 + (n0 >> 1) + q;
                    #pragma unroll
                    for (int j = 0; j < 4; j++) {
                        int c = n0 + j * 8 + 2 * q;
                        float z0 = fmaxf(fmaf(acc[i][j][hf * 2],     sAl[c],     sBe[c]),     0.f);
                        float z1 = fmaxf(fmaf(acc[i][j][hf * 2 + 1], sAl[c + 1], sBe[c + 1]), 0.f);
                        __half h0, h1, l0, l1;
                        split_h(z0, h0, l0); split_h(z1, h1, l1);
                        zh[rb + j * 4] = pack_h(h0, h1);
                        zl[rb + j * 4] = pack_h(l0, l1);
                    }
                }
            }
        }
        buf ^= 1;
    }
}

// ---------------- GEMM2: h = BN_o(z @ W2 + b2)(+relu),  [N,256]x[256,128] --------
// 512 thr, 16 warps: 2m x 8n, warp tile m32 x n16; M-tile 64; chunk double buffer
// 2-term: (Zh + Zl) x W16, 8 MMAs/kstep
__global__ void __launch_bounds__(512, 1) k_gemm2(
    int layer, const float* __restrict__ bias,
    const float* __restrict__ bn_g, const float* __restrict__ bn_b,
    const float* __restrict__ bn_m, const float* __restrict__ bn_v,
    float* __restrict__ out, int relu)
{
    extern __shared__ char sm[];
    uint32_t sb = smem_u32(sm);
    int tid = threadIdx.x, lane = tid & 31, wid = tid >> 5;

    g2_issue(sb, tid, blockIdx.x << 6, 0, 0);   // chunk0 of first tile -> buf0

    {   // W2 into padded smem [n=128][k=256]
        const uint4* s = (const uint4*)(g_w2t + (size_t)layer * 32768);
        #pragma unroll 2
        for (int i = tid; i < 4096; i += 512) {
            int r = i >> 5, c = i & 31;
            *(uint4*)(sm + G2_W + r * STR2B + c * 16) = s[i];
        }
    }
    float* sAl = (float*)(sm + G2_ALPHA);
    float* sBe = (float*)(sm + G2_BETA);
    if (tid < 128) {
        float s = bn_g[tid] * rsqrtf(bn_v[tid] + BN_EPS);
        sAl[tid] = s;
        sBe[tid] = (bias[tid] - bn_m[tid]) * s + bn_b[tid];
    }
    __syncthreads();

    int m0 = (wid >> 3) * 32, n0 = (wid & 7) * 16;
    uint32_t aoff = (uint32_t)((m0 + (lane & 15)) * STR1B + ((lane >> 4) << 4));
    uint32_t boff = (uint32_t)((n0 + ((lane >> 4) << 3) + (lane & 7)) * STR2B + (((lane >> 3) & 1) << 4));
    uint32_t aW = sb + G2_W + boff;
    int q = lane & 3;

    int buf = 0;
    for (int tile = blockIdx.x; tile < NT; tile += gridDim.x) {
        int row0 = tile << 6;

        float acc[2][2][4];
        #pragma unroll
        for (int i = 0; i < 2; i++)
            #pragma unroll
            for (int j = 0; j < 2; j++)
                #pragma unroll
                for (int f = 0; f < 4; f++) acc[i][j][f] = 0.f;

        #pragma unroll 1
        for (int ch = 0; ch < 2; ch++) {
            uint32_t chb = (uint32_t)ch * 256;
            CP_WAIT0();
            __syncthreads();
            // prefetch: next chunk of this tile, or chunk0 of next tile
            if (ch == 0) g2_issue(sb, tid, row0, 1, buf ^ 1);
            else         g2_issue(sb, tid, (tile + gridDim.x) << 6, 0, buf ^ 1);

            uint32_t aZH = sb + G2_Z + buf * G2_BUF + aoff;
            uint32_t aZL = aZH + G2_LO;

            #pragma unroll 2
            for (int ks = 0; ks < 8; ks++) {
                uint32_t kb = (uint32_t)ks << 5;
                uint32_t Ah[2][4], Alr[2][4], B[4];
                #pragma unroll
                for (int i = 0; i < 2; i++) {
                    LDSM_X4(Ah[i][0], Ah[i][1], Ah[i][2], Ah[i][3], aZH + i * (16 * STR1B) + kb);
                    LDSM_X4(Alr[i][0], Alr[i][1], Alr[i][2], Alr[i][3], aZL + i * (16 * STR1B) + kb);
                }
                LDSM_X4(B[0], B[1], B[2], B[3], aW + chb + kb);
                #pragma unroll
                for (int i = 0; i < 2; i++)
                    #pragma unroll
                    for (int j = 0; j < 2; j++)
                        mma_h32(acc[i][j][0], acc[i][j][1], acc[i][j][2], acc[i][j][3],
                                Ah[i][0], Ah[i][1], Ah[i][2], Ah[i][3],
                                B[j*2], B[j*2+1]);
                #pragma unroll
                for (int i = 0; i < 2; i++)
                    #pragma unroll
                    for (int j = 0; j < 2; j++)
                        mma_h32(acc[i][j][0], acc[i][j][1], acc[i][j][2], acc[i][j][3],
                                Alr[i][0], Alr[i][1], Alr[i][2], Alr[i][3],
                                B[j*2], B[j*2+1]);
            }
            buf ^= 1;
        }

        // epilogue: BN (+relu), fp32 store
        #pragma unroll
        for (int i = 0; i < 2; i++) {
            #pragma unroll
            for (int hf = 0; hf < 2; hf++) {
                int r = row0 + m0 + i * 16 + (lane >> 2) + hf * 8;
                if (r < N_NODES) {
                    float* dst = out + (size_t)r * 128;
                    #pragma unroll
                    for (int j = 0; j < 2; j++) {
                        int c = n0 + j * 8 + 2 * q;
                        float z0 = fmaf(acc[i][j][hf * 2],     sAl[c],     sBe[c]);
                        float z1 = fmaf(acc[i][j][hf * 2 + 1], sAl[c + 1], sBe[c + 1]);
                        if (relu) { z0 = fmaxf(z0, 0.f); z1 = fmaxf(z1, 0.f); }
                        *(float2*)(dst + c) = make_float2(z0, z1);
                    }
                }
            }
        }
    }
}

// ---------------- launch ----------------------------------------------------------
extern "C" void kernel_launch(void* const* d_in, const int* in_sizes, int n_in,
                              void* d_out, int out_size) {
    const float* x     = (const float*)d_in[0];
    const int*   ei    = (const int*)d_in[1];
    const float* W1    = (const float*)d_in[2];
    const float* b1    = (const float*)d_in[3];
    const float* bn1_g = (const float*)d_in[4];
    const float* bn1_b = (const float*)d_in[5];
    const float* bn1_m = (const float*)d_in[6];
    const float* bn1_v = (const float*)d_in[7];
    const float* W2    = (const float*)d_in[8];
    const float* b2    = (const float*)d_in[9];
    const float* bno_g = (const float*)d_in[10];
    const float* bno_b = (const float*)d_in[11];
    const float* bno_m = (const float*)d_in[12];
    const float* bno_v = (const float*)d_in[13];
    float* out = (float*)d_out;

    cudaFuncSetAttribute(k_gemm1, cudaFuncAttributeMaxDynamicSharedMemorySize, SMEM1);
    cudaFuncSetAttribute(k_gemm2, cudaFuncAttributeMaxDynamicSharedMemorySize, SMEM2);

    const int* src = ei;
    const int* dst = ei + EDGES;

    k_prep<<<1280, 256>>>(W1, W2);
    k_hist<<<(EDGES + 255) / 256, 256>>>(dst);
    k_scan<<<NSCAN, 1024>>>();
    k_fill<<<(EDGES + 255) / 256, 256>>>(src, dst);

    const float* h = x;
    for (int l = 0; l < LAYERS; l++) {
        k_aggregate<<<(N_NODES * 32 + 255) / 256, 256>>>(h);
        k_gemm1<<<GRID_G, 512, SMEM1>>>(l, b1 + (size_t)l * 256,
                bn1_g + (size_t)l * 256, bn1_b + (size_t)l * 256,
                bn1_m + (size_t)l * 256, bn1_v + (size_t)l * 256);
        k_gemm2<<<GRID_G, 512, SMEM2>>>(l, b2 + (size_t)l * 128,
                bno_g + (size_t)l * 128, bno_b + (size_t)l * 128,
                bno_m + (size_t)l * 128, bno_v + (size_t)l * 128,
                out, (l != LAYERS - 1) ? 1 : 0);
        h = out;
    }
}

// round 16
// speedup vs baseline: 1.1321x; 1.1321x over previous
#include <cuda_runtime.h>
#include <cuda_fp16.h>
#include <cstdint>

#define N_NODES 100000
#define EDGES   640000
#define LAYERS  5
#define BN_EPS  1e-5f
#define NT      1563         // ceil(100000/64): M-tile 64 for both GEMMs
#define GRID_G  148
#define NSCAN   98

// ---------------- static scratch ------------------------------------------------
__device__ __half g_a_hi[(size_t)N_NODES * 128];
__device__ __half g_a_lo[(size_t)N_NODES * 128];
__device__ __half g_z_hi[(size_t)N_NODES * 256];
__device__ __half g_z_lo[(size_t)N_NODES * 256];
__device__ __half g_w1t[LAYERS * 32768];   // [l][n=256][k=128], single fp16 plane
__device__ __half g_w2t[LAYERS * 32768];   // [l][n=128][k=256], single fp16 plane
__device__ int g_rowptr[N_NODES + 1];
__device__ int g_cnt[N_NODES];
__device__ int g_cursor[N_NODES];
__device__ int g_srcs[EDGES];
__device__ int g_part[NSCAN];

// ---------------- helpers -------------------------------------------------------
__device__ __forceinline__ uint32_t smem_u32(const void* p) {
    uint32_t a;
    asm("{ .reg .u64 t; cvta.to.shared.u64 t, %1; cvt.u32.u64 %0, t; }" : "=r"(a) : "l"(p));
    return a;
}
__device__ __forceinline__ uint32_t pack_h(__half a, __half b) {
    return ((uint32_t)__half_as_ushort(b) << 16) | (uint32_t)__half_as_ushort(a);
}
__device__ __forceinline__ void split_h(float x, __half& h, __half& l) {
    h = __float2half(x);
    l = __float2half(x - __half2float(h));
}

#define LDSM_X4(r0, r1, r2, r3, addr) \
    asm volatile("ldmatrix.sync.aligned.m8n8.x4.shared.b16 {%0,%1,%2,%3}, [%4];" \
        : "=r"(r0), "=r"(r1), "=r"(r2), "=r"(r3) : "r"(addr))

__device__ __forceinline__ void mma_h32(float& c0, float& c1, float& c2, float& c3,
        uint32_t a0, uint32_t a1, uint32_t a2, uint32_t a3, uint32_t b0, uint32_t b1) {
    asm volatile("mma.sync.aligned.m16n8k16.row.col.f32.f16.f16.f32 "
        "{%0,%1,%2,%3}, {%4,%5,%6,%7}, {%8,%9}, {%0,%1,%2,%3};"
        : "+f"(c0), "+f"(c1), "+f"(c2), "+f"(c3)
        : "r"(a0), "r"(a1), "r"(a2), "r"(a3), "r"(b0), "r"(b1));
}

__device__ __forceinline__ void cp16(uint32_t dst, const void* src, uint32_t srcsz) {
    asm volatile("cp.async.ca.shared.global [%0], [%1], 16, %2;"
                 :: "r"(dst), "l"(src), "r"(srcsz) : "memory");
}
#define CP_COMMIT() asm volatile("cp.async.commit_group;" ::: "memory")
#define CP_WAIT0()  asm volatile("cp.async.wait_group 0;" ::: "memory")

// ---------------- prep: W fp16 transpose + CSR zero (fused) ----------------------
__global__ void k_prep(const float* __restrict__ W1, const float* __restrict__ W2) {
    int i = blockIdx.x * blockDim.x + threadIdx.x;
    const int TOT = LAYERS * 32768;
    if (i < N_NODES) { g_cnt[i] = 0; g_cursor[i] = 0; }
    if (i < TOT) {
        int l = i >> 15, r = i & 32767;
        int k = r >> 8, n = r & 255;           // W1[l][k][n]
        g_w1t[(size_t)l * 32768 + n * 128 + k] = __float2half(W1[i]);
    } else if (i < 2 * TOT) {
        int j = i - TOT;
        int l = j >> 15, r = j & 32767;
        int k = r >> 7, n = r & 127;           // W2[l][k][n]
        g_w2t[(size_t)l * 32768 + n * 256 + k] = __float2half(W2[j]);
    }
}

// ---------------- CSR build ------------------------------------------------------
__global__ void k_hist(const int* __restrict__ dst) {
    int e = blockIdx.x * blockDim.x + threadIdx.x;
    if (e < EDGES) atomicAdd(&g_cnt[dst[e]], 1);
}
__global__ void k_scan_a() {
    __shared__ int s[1024];
    int t = threadIdx.x, b = blockIdx.x;
    int i = b * 1024 + t;
    int v = (i < N_NODES) ? g_cnt[i] : 0;
    s[t] = v;
    __syncthreads();
    #pragma unroll
    for (int off = 1; off < 1024; off <<= 1) {
        int u = (t >= off) ? s[t - off] : 0;
        __syncthreads();
        s[t] += u;
        __syncthreads();
    }
    if (i < N_NODES) g_rowptr[i + 1] = s[t];
    if (t == 1023) g_part[b] = s[t];
}
__global__ void k_scan_c() {
    __shared__ int pre;
    int t = threadIdx.x, b = blockIdx.x;
    if (t == 0) {
        int acc = 0;
        for (int j = 0; j < b; j++) acc += g_part[j];
        pre = acc;
    }
    __syncthreads();
    int i = b * 1024 + t;
    if (i < N_NODES) g_rowptr[i + 1] += pre;
    if (i == 0) g_rowptr[0] = 0;
}
__global__ void k_fill(const int* __restrict__ src, const int* __restrict__ dst) {
    int e = blockIdx.x * blockDim.x + threadIdx.x;
    if (e < EDGES) {
        int d = dst[e];
        int p = g_rowptr[d] + atomicAdd(&g_cursor[d], 1);
        g_srcs[p] = src[e];
    }
}

// ---------------- aggregation: agg = h_i + sum h_j -> split fp16 -----------------
__global__ void k_aggregate(const float* __restrict__ h) {
    int gw = (blockIdx.x * blockDim.x + threadIdx.x) >> 5;
    int lane = threadIdx.x & 31;
    if (gw >= N_NODES) return;
    const float4* hv = (const float4*)h;
    float4 acc = __ldg(&hv[(size_t)gw * 32 + lane]);
    int e0 = g_rowptr[gw], e1 = g_rowptr[gw + 1];
    for (int e = e0; e < e1; e++) {
        int j = g_srcs[e];
        float4 v = __ldg(&hv[(size_t)j * 32 + lane]);
        acc.x += v.x; acc.y += v.y; acc.z += v.z; acc.w += v.w;
    }
    __half h0, h1, h2, h3, l0, l1, l2, l3;
    split_h(acc.x, h0, l0); split_h(acc.y, h1, l1);
    split_h(acc.z, h2, l2); split_h(acc.w, h3, l3);
    uint2 ph, pl;
    ph.x = pack_h(h0, h1); ph.y = pack_h(h2, h3);
    pl.x = pack_h(l0, l1); pl.y = pack_h(l2, l3);
    ((uint2*)g_a_hi)[(size_t)gw * 32 + lane] = ph;
    ((uint2*)g_a_lo)[(size_t)gw * 32 + lane] = pl;
}

// ---------------- SMEM layouts ----------------------------------------------------
// GEMM1: alpha|beta | W [256][272] | A double buf [2][hi/lo][64][272]
#define STR1B    272
#define G1_ALPHA 0
#define G1_BETA  1024
#define G1_W     2048
#define G1_A     71680
#define G1_BUF   34816
#define G1_LO    17408
#define SMEM1    141312
// GEMM2: W [128][528] | chunk double buf [2][hi/lo][64][272] | alpha|beta
#define STR2B    528
#define G2_W     0
#define G2_Z     67584
#define G2_BUF   34816
#define G2_LO    17408
#define G2_ALPHA 137216
#define G2_BETA  137728
#define SMEM2    138240

// ---- cp.async full-tile issuers: one commit group per issue ---------------------
__device__ __forceinline__ void g1_issue(uint32_t sb, int tid, int row0, int buf) {
    int hl = tid >> 8;
    int t = tid & 255;
    int r = t >> 2, c = t & 3;
    int gr = row0 + r;
    uint32_t p = (gr < N_NODES) ? 16u : 0u;
    const char* gsrc = (const char*)(hl ? g_a_lo : g_a_hi) + (size_t)gr * 256 + c * 16;
    uint32_t dsm = sb + G1_A + buf * G1_BUF + hl * G1_LO + r * STR1B + c * 16;
    #pragma unroll
    for (int g = 0; g < 4; g++) cp16(dsm + g * 64, gsrc + g * 64, p);
    CP_COMMIT();
}
__device__ __forceinline__ void g2_issue(uint32_t sb, int tid, int row0, int ch, int buf) {
    int hl = tid >> 8;
    int t = tid & 255;
    int r = t >> 2, c = t & 3;
    int gr = row0 + r;
    uint32_t p = (gr < N_NODES) ? 16u : 0u;
    const char* gsrc = (const char*)(hl ? g_z_lo : g_z_hi) + (size_t)gr * 512 + ch * 256 + c * 16;
    uint32_t dsm = sb + G2_Z + buf * G2_BUF + hl * G2_LO + r * STR1B + c * 16;
    #pragma unroll
    for (int g = 0; g < 4; g++) cp16(dsm + g * 64, gsrc + g * 64, p);
    CP_COMMIT();
}

// ---------------- GEMM1: z = relu(BN1(agg @ W1 + b1)),  [N,128]x[128,256] --------
// 512 thr, 16 warps: 2m x 8n, warp tile m32 x n32; M-tile 64; double-buffered A
// 2-term: (Ah + Al) x W16, 16 MMAs/kstep
__global__ void __launch_bounds__(512, 1) k_gemm1(
    int layer, const float* __restrict__ bias,
    const float* __restrict__ bn_g, const float* __restrict__ bn_b,
    const float* __restrict__ bn_m, const float* __restrict__ bn_v)
{
    extern __shared__ char sm[];
    uint32_t sb = smem_u32(sm);
    int tid = threadIdx.x, lane = tid & 31, wid = tid >> 5;

    g1_issue(sb, tid, blockIdx.x << 6, 0);   // prefetch first tile into buf0

    {   // W into padded smem [n=256][k=128]
        const uint4* s = (const uint4*)(g_w1t + (size_t)layer * 32768);
        #pragma unroll 2
        for (int i = tid; i < 4096; i += 512) {
            int r = i >> 4, c = i & 15;
            *(uint4*)(sm + G1_W + r * STR1B + c * 16) = s[i];
        }
    }
    float* sAl = (float*)(sm + G1_ALPHA);
    float* sBe = (float*)(sm + G1_BETA);
    if (tid < 256) {
        float s = bn_g[tid] * rsqrtf(bn_v[tid] + BN_EPS);
        sAl[tid] = s;
        sBe[tid] = (bias[tid] - bn_m[tid]) * s + bn_b[tid];
    }
    __syncthreads();

    int m0 = (wid >> 3) * 32, n0 = (wid & 7) * 32;
    uint32_t aoffA = (uint32_t)((m0 + (lane & 15)) * STR1B + ((lane >> 4) << 4));
    uint32_t boff = (uint32_t)((n0 + ((lane >> 4) << 3) + (lane & 7)) * STR1B + (((lane >> 3) & 1) << 4));
    uint32_t aW = sb + G1_W + boff;
    int q = lane & 3;

    int buf = 0;
    for (int tile = blockIdx.x; tile < NT; tile += gridDim.x) {
        int row0 = tile << 6;
        CP_WAIT0();            // current buffer ready
        __syncthreads();       // all warps past previous tile's reads
        g1_issue(sb, tid, (tile + gridDim.x) << 6, buf ^ 1);   // prefetch next

        uint32_t aAH = sb + G1_A + buf * G1_BUF + aoffA;
        uint32_t aAL = aAH + G1_LO;

        float acc[2][4][4];
        #pragma unroll
        for (int i = 0; i < 2; i++)
            #pragma unroll
            for (int j = 0; j < 4; j++)
                #pragma unroll
                for (int f = 0; f < 4; f++) acc[i][j][f] = 0.f;

        #pragma unroll 2
        for (int ks = 0; ks < 8; ks++) {
            uint32_t kb = (uint32_t)ks << 5;
            uint32_t Ah[2][4], Alr[2][4], B[4];
            #pragma unroll
            for (int i = 0; i < 2; i++) {
                LDSM_X4(Ah[i][0], Ah[i][1], Ah[i][2], Ah[i][3], aAH + i * (16 * STR1B) + kb);
                LDSM_X4(Alr[i][0], Alr[i][1], Alr[i][2], Alr[i][3], aAL + i * (16 * STR1B) + kb);
            }
            #pragma unroll
            for (int j2 = 0; j2 < 2; j2++) {
                LDSM_X4(B[0], B[1], B[2], B[3], aW + j2 * (16 * STR1B) + kb);
                #pragma unroll
                for (int i = 0; i < 2; i++)
                    #pragma unroll
                    for (int jj = 0; jj < 2; jj++)
                        mma_h32(acc[i][j2*2+jj][0], acc[i][j2*2+jj][1],
                                acc[i][j2*2+jj][2], acc[i][j2*2+jj][3],
                                Ah[i][0], Ah[i][1], Ah[i][2], Ah[i][3],
                                B[jj*2], B[jj*2+1]);
                #pragma unroll
                for (int i = 0; i < 2; i++)
                    #pragma unroll
                    for (int jj = 0; jj < 2; jj++)
                        mma_h32(acc[i][j2*2+jj][0], acc[i][j2*2+jj][1],
                                acc[i][j2*2+jj][2], acc[i][j2*2+jj][3],
                                Alr[i][0], Alr[i][1], Alr[i][2], Alr[i][3],
                                B[jj*2], B[jj*2+1]);
            }
        }

        // epilogue: BN + relu + split-fp16 store of z (overlaps inflight prefetch)
        uint32_t* zh = (uint32_t*)g_z_hi;
        uint32_t* zl = (uint32_t*)g_z_lo;
        #pragma unroll
        for (int i = 0; i < 2; i++) {
            #pragma unroll
            for (int hf = 0; hf < 2; hf++) {
                int r = row0 + m0 + i * 16 + (lane >> 2) + hf * 8;
                if (r < N_NODES) {
                    size_t rb = (size_t)r * 128 + (n0 >> 1) + q;
                    #pragma unroll
                    for (int j = 0; j < 4; j++) {
                        int c = n0 + j * 8 + 2 * q;
                        float z0 = fmaxf(fmaf(acc[i][j][hf * 2],     sAl[c],     sBe[c]),     0.f);
                        float z1 = fmaxf(fmaf(acc[i][j][hf * 2 + 1], sAl[c + 1], sBe[c + 1]), 0.f);
                        __half h0, h1, l0, l1;
                        split_h(z0, h0, l0); split_h(z1, h1, l1);
                        zh[rb + j * 4] = pack_h(h0, h1);
                        zl[rb + j * 4] = pack_h(l0, l1);
                    }
                }
            }
        }
        buf ^= 1;
    }
}

// ---------------- GEMM2: h = BN_o(z @ W2 + b2)(+relu),  [N,256]x[256,128] --------
// 512 thr, 16 warps: 2m x 8n, warp tile m32 x n16; M-tile 64; chunk double buffer
// 2-term: (Zh + Zl) x W16, 8 MMAs/kstep
__global__ void __launch_bounds__(512, 1) k_gemm2(
    int layer, const float* __restrict__ bias,
    const float* __restrict__ bn_g, const float* __restrict__ bn_b,
    const float* __restrict__ bn_m, const float* __restrict__ bn_v,
    float* __restrict__ out, int relu)
{
    extern __shared__ char sm[];
    uint32_t sb = smem_u32(sm);
    int tid = threadIdx.x, lane = tid & 31, wid = tid >> 5;

    g2_issue(sb, tid, blockIdx.x << 6, 0, 0);   // chunk0 of first tile -> buf0

    {   // W2 into padded smem [n=128][k=256]
        const uint4* s = (const uint4*)(g_w2t + (size_t)layer * 32768);
        #pragma unroll 2
        for (int i = tid; i < 4096; i += 512) {
            int r = i >> 5, c = i & 31;
            *(uint4*)(sm + G2_W + r * STR2B + c * 16) = s[i];
        }
    }
    float* sAl = (float*)(sm + G2_ALPHA);
    float* sBe = (float*)(sm + G2_BETA);
    if (tid < 128) {
        float s = bn_g[tid] * rsqrtf(bn_v[tid] + BN_EPS);
        sAl[tid] = s;
        sBe[tid] = (bias[tid] - bn_m[tid]) * s + bn_b[tid];
    }
    __syncthreads();

    int m0 = (wid >> 3) * 32, n0 = (wid & 7) * 16;
    uint32_t aoff = (uint32_t)((m0 + (lane & 15)) * STR1B + ((lane >> 4) << 4));
    uint32_t boff = (uint32_t)((n0 + ((lane >> 4) << 3) + (lane & 7)) * STR2B + (((lane >> 3) & 1) << 4));
    uint32_t aW = sb + G2_W + boff;
    int q = lane & 3;

    int buf = 0;
    for (int tile = blockIdx.x; tile < NT; tile += gridDim.x) {
        int row0 = tile << 6;

        float acc[2][2][4];
        #pragma unroll
        for (int i = 0; i < 2; i++)
            #pragma unroll
            for (int j = 0; j < 2; j++)
                #pragma unroll
                for (int f = 0; f < 4; f++) acc[i][j][f] = 0.f;

        #pragma unroll 1
        for (int ch = 0; ch < 2; ch++) {
            uint32_t chb = (uint32_t)ch * 256;
            CP_WAIT0();
            __syncthreads();
            // prefetch: next chunk of this tile, or chunk0 of next tile
            if (ch == 0) g2_issue(sb, tid, row0, 1, buf ^ 1);
            else         g2_issue(sb, tid, (tile + gridDim.x) << 6, 0, buf ^ 1);

            uint32_t aZH = sb + G2_Z + buf * G2_BUF + aoff;
            uint32_t aZL = aZH + G2_LO;

            #pragma unroll 2
            for (int ks = 0; ks < 8; ks++) {
                uint32_t kb = (uint32_t)ks << 5;
                uint32_t Ah[2][4], Alr[2][4], B[4];
                #pragma unroll
                for (int i = 0; i < 2; i++) {
                    LDSM_X4(Ah[i][0], Ah[i][1], Ah[i][2], Ah[i][3], aZH + i * (16 * STR1B) + kb);
                    LDSM_X4(Alr[i][0], Alr[i][1], Alr[i][2], Alr[i][3], aZL + i * (16 * STR1B) + kb);
                }
                LDSM_X4(B[0], B[1], B[2], B[3], aW + chb + kb);
                #pragma unroll
                for (int i = 0; i < 2; i++)
                    #pragma unroll
                    for (int j = 0; j < 2; j++)
                        mma_h32(acc[i][j][0], acc[i][j][1], acc[i][j][2], acc[i][j][3],
                                Ah[i][0], Ah[i][1], Ah[i][2], Ah[i][3],
                                B[j*2], B[j*2+1]);
                #pragma unroll
                for (int i = 0; i < 2; i++)
                    #pragma unroll
                    for (int j = 0; j < 2; j++)
                        mma_h32(acc[i][j][0], acc[i][j][1], acc[i][j][2], acc[i][j][3],
                                Alr[i][0], Alr[i][1], Alr[i][2], Alr[i][3],
                                B[j*2], B[j*2+1]);
            }
            buf ^= 1;
        }

        // epilogue: BN (+relu), fp32 store
        #pragma unroll
        for (int i = 0; i < 2; i++) {
            #pragma unroll
            for (int hf = 0; hf < 2; hf++) {
                int r = row0 + m0 + i * 16 + (lane >> 2) + hf * 8;
                if (r < N_NODES) {
                    float* dst = out + (size_t)r * 128;
                    #pragma unroll
                    for (int j = 0; j < 2; j++) {
                        int c = n0 + j * 8 + 2 * q;
                        float z0 = fmaf(acc[i][j][hf * 2],     sAl[c],     sBe[c]);
                        float z1 = fmaf(acc[i][j][hf * 2 + 1], sAl[c + 1], sBe[c + 1]);
                        if (relu) { z0 = fmaxf(z0, 0.f); z1 = fmaxf(z1, 0.f); }
                        *(float2*)(dst + c) = make_float2(z0, z1);
                    }
                }
            }
        }
    }
}

// ---------------- launch ----------------------------------------------------------
extern "C" void kernel_launch(void* const* d_in, const int* in_sizes, int n_in,
                              void* d_out, int out_size) {
    const float* x     = (const float*)d_in[0];
    const int*   ei    = (const int*)d_in[1];
    const float* W1    = (const float*)d_in[2];
    const float* b1    = (const float*)d_in[3];
    const float* bn1_g = (const float*)d_in[4];
    const float* bn1_b = (const float*)d_in[5];
    const float* bn1_m = (const float*)d_in[6];
    const float* bn1_v = (const float*)d_in[7];
    const float* W2    = (const float*)d_in[8];
    const float* b2    = (const float*)d_in[9];
    const float* bno_g = (const float*)d_in[10];
    const float* bno_b = (const float*)d_in[11];
    const float* bno_m = (const float*)d_in[12];
    const float* bno_v = (const float*)d_in[13];
    float* out = (float*)d_out;

    cudaFuncSetAttribute(k_gemm1, cudaFuncAttributeMaxDynamicSharedMemorySize, SMEM1);
    cudaFuncSetAttribute(k_gemm2, cudaFuncAttributeMaxDynamicSharedMemorySize, SMEM2);

    const int* src = ei;
    const int* dst = ei + EDGES;

    k_prep<<<1280, 256>>>(W1, W2);
    k_hist<<<(EDGES + 255) / 256, 256>>>(dst);
    k_scan_a<<<NSCAN, 1024>>>();
    k_scan_c<<<NSCAN, 1024>>>();
    k_fill<<<(EDGES + 255) / 256, 256>>>(src, dst);

    const float* h = x;
    for (int l = 0; l < LAYERS; l++) {
        k_aggregate<<<(N_NODES * 32 + 255) / 256, 256>>>(h);
        k_gemm1<<<GRID_G, 512, SMEM1>>>(l, b1 + (size_t)l * 256,
                bn1_g + (size_t)l * 256, bn1_b + (size_t)l * 256,
                bn1_m + (size_t)l * 256, bn1_v + (size_t)l * 256);
        k_gemm2<<<GRID_G, 512, SMEM2>>>(l, b2 + (size_t)l * 128,
                bno_g + (size_t)l * 128, bno_b + (size_t)l * 128,
                bno_m + (size_t)l * 128, bno_v + (size_t)l * 128,
                out, (l != LAYERS - 1) ? 1 : 0);
        h = out;
    }
}

// round 17
// speedup vs baseline: 1.1363x; 1.0037x over previous
#include <cuda_runtime.h>
#include <cuda_fp16.h>
#include <cstdint>

#define N_NODES 100000
#define EDGES   640000
#define LAYERS  5
#define BN_EPS  1e-5f
#define NT      1563         // ceil(100000/64): M-tile 64 for both GEMMs
#define GRID_G  148
#define NSCAN   98

// ---------------- static scratch ------------------------------------------------
__device__ __half g_a_hi[(size_t)N_NODES * 128];
__device__ __half g_a_lo[(size_t)N_NODES * 128];
__device__ __half g_z_hi[(size_t)N_NODES * 256];
__device__ __half g_z_lo[(size_t)N_NODES * 256];
__device__ __half g_w1t[LAYERS * 32768];   // [l][n=256][k=128], single fp16 plane
__device__ __half g_w2t[LAYERS * 32768];   // [l][n=128][k=256], single fp16 plane
__device__ int g_rowptr[N_NODES + 1];
__device__ int g_cnt[N_NODES];
__device__ int g_cursor[N_NODES];
__device__ int g_srcs[EDGES];
__device__ int g_part[NSCAN];

// ---------------- helpers -------------------------------------------------------
__device__ __forceinline__ uint32_t smem_u32(const void* p) {
    uint32_t a;
    asm("{ .reg .u64 t; cvta.to.shared.u64 t, %1; cvt.u32.u64 %0, t; }" : "=r"(a) : "l"(p));
    return a;
}
__device__ __forceinline__ uint32_t pack_h(__half a, __half b) {
    return ((uint32_t)__half_as_ushort(b) << 16) | (uint32_t)__half_as_ushort(a);
}
__device__ __forceinline__ void split_h(float x, __half& h, __half& l) {
    h = __float2half(x);
    l = __float2half(x - __half2float(h));
}

#define LDSM_X4(r0, r1, r2, r3, addr) \
    asm volatile("ldmatrix.sync.aligned.m8n8.x4.shared.b16 {%0,%1,%2,%3}, [%4];" \
        : "=r"(r0), "=r"(r1), "=r"(r2), "=r"(r3) : "r"(addr))

__device__ __forceinline__ void mma_h32(float& c0, float& c1, float& c2, float& c3,
        uint32_t a0, uint32_t a1, uint32_t a2, uint32_t a3, uint32_t b0, uint32_t b1) {
    asm volatile("mma.sync.aligned.m16n8k16.row.col.f32.f16.f16.f32 "
        "{%0,%1,%2,%3}, {%4,%5,%6,%7}, {%8,%9}, {%0,%1,%2,%3};"
        : "+f"(c0), "+f"(c1), "+f"(c2), "+f"(c3)
        : "r"(a0), "r"(a1), "r"(a2), "r"(a3), "r"(b0), "r"(b1));
}

__device__ __forceinline__ void cp16(uint32_t dst, const void* src, uint32_t srcsz) {
    asm volatile("cp.async.ca.shared.global [%0], [%1], 16, %2;"
                 :: "r"(dst), "l"(src), "r"(srcsz) : "memory");
}
#define CP_COMMIT() asm volatile("cp.async.commit_group;" ::: "memory")
#define CP_WAIT0()  asm volatile("cp.async.wait_group 0;" ::: "memory")

// ---------------- prep: W fp16 transpose + CSR zero (fused) ----------------------
__global__ void k_prep(const float* __restrict__ W1, const float* __restrict__ W2) {
    int i = blockIdx.x * blockDim.x + threadIdx.x;
    const int TOT = LAYERS * 32768;
    if (i < N_NODES) { g_cnt[i] = 0; g_cursor[i] = 0; }
    if (i < TOT) {
        int l = i >> 15, r = i & 32767;
        int k = r >> 8, n = r & 255;           // W1[l][k][n]
        g_w1t[(size_t)l * 32768 + n * 128 + k] = __float2half(W1[i]);
    } else if (i < 2 * TOT) {
        int j = i - TOT;
        int l = j >> 15, r = j & 32767;
        int k = r >> 7, n = r & 127;           // W2[l][k][n]
        g_w2t[(size_t)l * 32768 + n * 256 + k] = __float2half(W2[j]);
    }
}

// ---------------- CSR build ------------------------------------------------------
__global__ void k_hist(const int* __restrict__ dst) {
    int e = blockIdx.x * blockDim.x + threadIdx.x;
    if (e < EDGES) atomicAdd(&g_cnt[dst[e]], 1);
}
__global__ void k_scan_a() {
    __shared__ int s[1024];
    int t = threadIdx.x, b = blockIdx.x;
    int i = b * 1024 + t;
    int v = (i < N_NODES) ? g_cnt[i] : 0;
    s[t] = v;
    __syncthreads();
    #pragma unroll
    for (int off = 1; off < 1024; off <<= 1) {
        int u = (t >= off) ? s[t - off] : 0;
        __syncthreads();
        s[t] += u;
        __syncthreads();
    }
    if (i < N_NODES) g_rowptr[i + 1] = s[t];
    if (t == 1023) g_part[b] = s[t];
}
__global__ void k_scan_c() {
    __shared__ int pre;
    int t = threadIdx.x, b = blockIdx.x;
    if (t == 0) {
        int acc = 0;
        for (int j = 0; j < b; j++) acc += g_part[j];
        pre = acc;
    }
    __syncthreads();
    int i = b * 1024 + t;
    if (i < N_NODES) g_rowptr[i + 1] += pre;
    if (i == 0) g_rowptr[0] = 0;
}
__global__ void k_fill(const int* __restrict__ src, const int* __restrict__ dst) {
    int e = blockIdx.x * blockDim.x + threadIdx.x;
    if (e < EDGES) {
        int d = dst[e];
        int p = g_rowptr[d] + atomicAdd(&g_cursor[d], 1);
        g_srcs[p] = src[e];
    }
}

// ---------------- aggregation: agg = h_i + sum h_j -> split fp16 -----------------
__global__ void k_aggregate(const float* __restrict__ h) {
    int gw = (blockIdx.x * blockDim.x + threadIdx.x) >> 5;
    int lane = threadIdx.x & 31;
    if (gw >= N_NODES) return;
    const float4* hv = (const float4*)h;
    float4 acc = __ldg(&hv[(size_t)gw * 32 + lane]);
    int e0 = g_rowptr[gw], e1 = g_rowptr[gw + 1];
    for (int e = e0; e < e1; e++) {
        int j = g_srcs[e];
        float4 v = __ldg(&hv[(size_t)j * 32 + lane]);
        acc.x += v.x; acc.y += v.y; acc.z += v.z; acc.w += v.w;
    }
    __half h0, h1, h2, h3, l0, l1, l2, l3;
    split_h(acc.x, h0, l0); split_h(acc.y, h1, l1);
    split_h(acc.z, h2, l2); split_h(acc.w, h3, l3);
    uint2 ph, pl;
    ph.x = pack_h(h0, h1); ph.y = pack_h(h2, h3);
    pl.x = pack_h(l0, l1); pl.y = pack_h(l2, l3);
    ((uint2*)g_a_hi)[(size_t)gw * 32 + lane] = ph;
    ((uint2*)g_a_lo)[(size_t)gw * 32 + lane] = pl;
}

// ---------------- SMEM layouts ----------------------------------------------------
// GEMM1: alpha|beta | W [256][272] | A double buf [2][hi/lo][64][272]
#define STR1B    272
#define G1_ALPHA 0
#define G1_BETA  1024
#define G1_W     2048
#define G1_A     71680
#define G1_BUF   34816
#define G1_LO    17408
#define SMEM1    141312
// GEMM2: W [128][528] | chunk double buf [2][hi/lo][64][272] | alpha|beta
#define STR2B    528
#define G2_W     0
#define G2_Z     67584
#define G2_BUF   34816
#define G2_LO    17408
#define G2_ALPHA 137216
#define G2_BETA  137728
#define SMEM2    138240

// ---- cp.async full-tile issuers: one commit group per issue ---------------------
__device__ __forceinline__ void g1_issue(uint32_t sb, int tid, int row0, int buf) {
    int hl = tid >> 8;
    int t = tid & 255;
    int r = t >> 2, c = t & 3;
    int gr = row0 + r;
    uint32_t p = (gr < N_NODES) ? 16u : 0u;
    const char* gsrc = (const char*)(hl ? g_a_lo : g_a_hi) + (size_t)gr * 256 + c * 16;
    uint32_t dsm = sb + G1_A + buf * G1_BUF + hl * G1_LO + r * STR1B + c * 16;
    #pragma unroll
    for (int g = 0; g < 4; g++) cp16(dsm + g * 64, gsrc + g * 64, p);
    CP_COMMIT();
}
__device__ __forceinline__ void g2_issue(uint32_t sb, int tid, int row0, int ch, int buf) {
    int hl = tid >> 8;
    int t = tid & 255;
    int r = t >> 2, c = t & 3;
    int gr = row0 + r;
    uint32_t p = (gr < N_NODES) ? 16u : 0u;
    const char* gsrc = (const char*)(hl ? g_z_lo : g_z_hi) + (size_t)gr * 512 + ch * 256 + c * 16;
    uint32_t dsm = sb + G2_Z + buf * G2_BUF + hl * G2_LO + r * STR1B + c * 16;
    #pragma unroll
    for (int g = 0; g < 4; g++) cp16(dsm + g * 64, gsrc + g * 64, p);
    CP_COMMIT();
}

// ---------------- GEMM1: z = relu(BN1(agg @ W1 + b1)),  [N,128]x[128,256] --------
// 512 thr, 16 warps: 2m x 8n, warp tile m32 x n32; M-tile 64; double-buffered A
// 2-term: (Ah + Al) x W16, 16 MMAs/kstep; k-loop unroll 4
__global__ void __launch_bounds__(512, 1) k_gemm1(
    int layer, const float* __restrict__ bias,
    const float* __restrict__ bn_g, const float* __restrict__ bn_b,
    const float* __restrict__ bn_m, const float* __restrict__ bn_v)
{
    extern __shared__ char sm[];
    uint32_t sb = smem_u32(sm);
    int tid = threadIdx.x, lane = tid & 31, wid = tid >> 5;

    g1_issue(sb, tid, blockIdx.x << 6, 0);   // prefetch first tile into buf0

    {   // W into padded smem [n=256][k=128]
        const uint4* s = (const uint4*)(g_w1t + (size_t)layer * 32768);
        #pragma unroll 2
        for (int i = tid; i < 4096; i += 512) {
            int r = i >> 4, c = i & 15;
            *(uint4*)(sm + G1_W + r * STR1B + c * 16) = s[i];
        }
    }
    float* sAl = (float*)(sm + G1_ALPHA);
    float* sBe = (float*)(sm + G1_BETA);
    if (tid < 256) {
        float s = bn_g[tid] * rsqrtf(bn_v[tid] + BN_EPS);
        sAl[tid] = s;
        sBe[tid] = (bias[tid] - bn_m[tid]) * s + bn_b[tid];
    }
    __syncthreads();

    int m0 = (wid >> 3) * 32, n0 = (wid & 7) * 32;
    uint32_t aoffA = (uint32_t)((m0 + (lane & 15)) * STR1B + ((lane >> 4) << 4));
    uint32_t boff = (uint32_t)((n0 + ((lane >> 4) << 3) + (lane & 7)) * STR1B + (((lane >> 3) & 1) << 4));
    uint32_t aW = sb + G1_W + boff;
    int q = lane & 3;

    int buf = 0;
    for (int tile = blockIdx.x; tile < NT; tile += gridDim.x) {
        int row0 = tile << 6;
        CP_WAIT0();            // current buffer ready
        __syncthreads();       // all warps past previous tile's reads
        g1_issue(sb, tid, (tile + gridDim.x) << 6, buf ^ 1);   // prefetch next

        uint32_t aAH = sb + G1_A + buf * G1_BUF + aoffA;
        uint32_t aAL = aAH + G1_LO;

        float acc[2][4][4];
        #pragma unroll
        for (int i = 0; i < 2; i++)
            #pragma unroll
            for (int j = 0; j < 4; j++)
                #pragma unroll
                for (int f = 0; f < 4; f++) acc[i][j][f] = 0.f;

        #pragma unroll 4
        for (int ks = 0; ks < 8; ks++) {
            uint32_t kb = (uint32_t)ks << 5;
            uint32_t Ah[2][4], Alr[2][4], B[4];
            #pragma unroll
            for (int i = 0; i < 2; i++) {
                LDSM_X4(Ah[i][0], Ah[i][1], Ah[i][2], Ah[i][3], aAH + i * (16 * STR1B) + kb);
                LDSM_X4(Alr[i][0], Alr[i][1], Alr[i][2], Alr[i][3], aAL + i * (16 * STR1B) + kb);
            }
            #pragma unroll
            for (int j2 = 0; j2 < 2; j2++) {
                LDSM_X4(B[0], B[1], B[2], B[3], aW + j2 * (16 * STR1B) + kb);
                #pragma unroll
                for (int i = 0; i < 2; i++)
                    #pragma unroll
                    for (int jj = 0; jj < 2; jj++)
                        mma_h32(acc[i][j2*2+jj][0], acc[i][j2*2+jj][1],
                                acc[i][j2*2+jj][2], acc[i][j2*2+jj][3],
                                Ah[i][0], Ah[i][1], Ah[i][2], Ah[i][3],
                                B[jj*2], B[jj*2+1]);
                #pragma unroll
                for (int i = 0; i < 2; i++)
                    #pragma unroll
                    for (int jj = 0; jj < 2; jj++)
                        mma_h32(acc[i][j2*2+jj][0], acc[i][j2*2+jj][1],
                                acc[i][j2*2+jj][2], acc[i][j2*2+jj][3],
                                Alr[i][0], Alr[i][1], Alr[i][2], Alr[i][3],
                                B[jj*2], B[jj*2+1]);
            }
        }

        // epilogue: BN + relu + split-fp16 store of z (overlaps inflight prefetch)
        uint32_t* zh = (uint32_t*)g_z_hi;
        uint32_t* zl = (uint32_t*)g_z_lo;
        #pragma unroll
        for (int i = 0; i < 2; i++) {
            #pragma unroll
            for (int hf = 0; hf < 2; hf++) {
                int r = row0 + m0 + i * 16 + (lane >> 2) + hf * 8;
                if (r < N_NODES) {
                    size_t rb = (size_t)r * 128 + (n0 >> 1) + q;
                    #pragma unroll
                    for (int j = 0; j < 4; j++) {
                        int c = n0 + j * 8 + 2 * q;
                        float z0 = fmaxf(fmaf(acc[i][j][hf * 2],     sAl[c],     sBe[c]),     0.f);
                        float z1 = fmaxf(fmaf(acc[i][j][hf * 2 + 1], sAl[c + 1], sBe[c + 1]), 0.f);
                        __half h0, h1, l0, l1;
                        split_h(z0, h0, l0); split_h(z1, h1, l1);
                        zh[rb + j * 4] = pack_h(h0, h1);
                        zl[rb + j * 4] = pack_h(l0, l1);
                    }
                }
            }
        }
        buf ^= 1;
    }
}

// ---------------- GEMM2: h = BN_o(z @ W2 + b2)(+relu),  [N,256]x[256,128] --------
// 512 thr, 16 warps: 2m x 8n, warp tile m32 x n16; M-tile 64; chunk double buffer
// 2-term: (Zh + Zl) x W16, 8 MMAs/kstep; k-loop unroll 4
__global__ void __launch_bounds__(512, 1) k_gemm2(
    int layer, const float* __restrict__ bias,
    const float* __restrict__ bn_g, const float* __restrict__ bn_b,
    const float* __restrict__ bn_m, const float* __restrict__ bn_v,
    float* __restrict__ out, int relu)
{
    extern __shared__ char sm[];
    uint32_t sb = smem_u32(sm);
    int tid = threadIdx.x, lane = tid & 31, wid = tid >> 5;

    g2_issue(sb, tid, blockIdx.x << 6, 0, 0);   // chunk0 of first tile -> buf0

    {   // W2 into padded smem [n=128][k=256]
        const uint4* s = (const uint4*)(g_w2t + (size_t)layer * 32768);
        #pragma unroll 2
        for (int i = tid; i < 4096; i += 512) {
            int r = i >> 5, c = i & 31;
            *(uint4*)(sm + G2_W + r * STR2B + c * 16) = s[i];
        }
    }
    float* sAl = (float*)(sm + G2_ALPHA);
    float* sBe = (float*)(sm + G2_BETA);
    if (tid < 128) {
        float s = bn_g[tid] * rsqrtf(bn_v[tid] + BN_EPS);
        sAl[tid] = s;
        sBe[tid] = (bias[tid] - bn_m[tid]) * s + bn_b[tid];
    }
    __syncthreads();

    int m0 = (wid >> 3) * 32, n0 = (wid & 7) * 16;
    uint32_t aoff = (uint32_t)((m0 + (lane & 15)) * STR1B + ((lane >> 4) << 4));
    uint32_t boff = (uint32_t)((n0 + ((lane >> 4) << 3) + (lane & 7)) * STR2B + (((lane >> 3) & 1) << 4));
    uint32_t aW = sb + G2_W + boff;
    int q = lane & 3;

    int buf = 0;
    for (int tile = blockIdx.x; tile < NT; tile += gridDim.x) {
        int row0 = tile << 6;

        float acc[2][2][4];
        #pragma unroll
        for (int i = 0; i < 2; i++)
            #pragma unroll
            for (int j = 0; j < 2; j++)
                #pragma unroll
                for (int f = 0; f < 4; f++) acc[i][j][f] = 0.f;

        #pragma unroll 1
        for (int ch = 0; ch < 2; ch++) {
            uint32_t chb = (uint32_t)ch * 256;
            CP_WAIT0();
            __syncthreads();
            // prefetch: next chunk of this tile, or chunk0 of next tile
            if (ch == 0) g2_issue(sb, tid, row0, 1, buf ^ 1);
            else         g2_issue(sb, tid, (tile + gridDim.x) << 6, 0, buf ^ 1);

            uint32_t aZH = sb + G2_Z + buf * G2_BUF + aoff;
            uint32_t aZL = aZH + G2_LO;

            #pragma unroll 4
            for (int ks = 0; ks < 8; ks++) {
                uint32_t kb = (uint32_t)ks << 5;
                uint32_t Ah[2][4], Alr[2][4], B[4];
                #pragma unroll
                for (int i = 0; i < 2; i++) {
                    LDSM_X4(Ah[i][0], Ah[i][1], Ah[i][2], Ah[i][3], aZH + i * (16 * STR1B) + kb);
                    LDSM_X4(Alr[i][0], Alr[i][1], Alr[i][2], Alr[i][3], aZL + i * (16 * STR1B) + kb);
                }
                LDSM_X4(B[0], B[1], B[2], B[3], aW + chb + kb);
                #pragma unroll
                for (int i = 0; i < 2; i++)
                    #pragma unroll
                    for (int j = 0; j < 2; j++)
                        mma_h32(acc[i][j][0], acc[i][j][1], acc[i][j][2], acc[i][j][3],
                                Ah[i][0], Ah[i][1], Ah[i][2], Ah[i][3],
                                B[j*2], B[j*2+1]);
                #pragma unroll
                for (int i = 0; i < 2; i++)
                    #pragma unroll
                    for (int j = 0; j < 2; j++)
                        mma_h32(acc[i][j][0], acc[i][j][1], acc[i][j][2], acc[i][j][3],
                                Alr[i][0], Alr[i][1], Alr[i][2], Alr[i][3],
                                B[j*2], B[j*2+1]);
            }
            buf ^= 1;
        }

        // epilogue: BN (+relu), fp32 store
        #pragma unroll
        for (int i = 0; i < 2; i++) {
            #pragma unroll
            for (int hf = 0; hf < 2; hf++) {
                int r = row0 + m0 + i * 16 + (lane >> 2) + hf * 8;
                if (r < N_NODES) {
                    float* dst = out + (size_t)r * 128;
                    #pragma unroll
                    for (int j = 0; j < 2; j++) {
                        int c = n0 + j * 8 + 2 * q;
                        float z0 = fmaf(acc[i][j][hf * 2],     sAl[c],     sBe[c]);
                        float z1 = fmaf(acc[i][j][hf * 2 + 1], sAl[c + 1], sBe[c + 1]);
                        if (relu) { z0 = fmaxf(z0, 0.f); z1 = fmaxf(z1, 0.f); }
                        *(float2*)(dst + c) = make_float2(z0, z1);
                    }
                }
            }
        }
    }
}

// ---------------- launch ----------------------------------------------------------
extern "C" void kernel_launch(void* const* d_in, const int* in_sizes, int n_in,
                              void* d_out, int out_size) {
    const float* x     = (const float*)d_in[0];
    const int*   ei    = (const int*)d_in[1];
    const float* W1    = (const float*)d_in[2];
    const float* b1    = (const float*)d_in[3];
    const float* bn1_g = (const float*)d_in[4];
    const float* bn1_b = (const float*)d_in[5];
    const float* bn1_m = (const float*)d_in[6];
    const float* bn1_v = (const float*)d_in[7];
    const float* W2    = (const float*)d_in[8];
    const float* b2    = (const float*)d_in[9];
    const float* bno_g = (const float*)d_in[10];
    const float* bno_b = (const float*)d_in[11];
    const float* bno_m = (const float*)d_in[12];
    const float* bno_v = (const float*)d_in[13];
    float* out = (float*)d_out;

    cudaFuncSetAttribute(k_gemm1, cudaFuncAttributeMaxDynamicSharedMemorySize, SMEM1);
    cudaFuncSetAttribute(k_gemm2, cudaFuncAttributeMaxDynamicSharedMemorySize, SMEM2);

    const int* src = ei;
    const int* dst = ei + EDGES;

    k_prep<<<1280, 256>>>(W1, W2);
    k_hist<<<(EDGES + 255) / 256, 256>>>(dst);
    k_scan_a<<<NSCAN, 1024>>>();
    k_scan_c<<<NSCAN, 1024>>>();
    k_fill<<<(EDGES + 255) / 256, 256>>>(src, dst);

    const float* h = x;
    for (int l = 0; l < LAYERS; l++) {
        k_aggregate<<<(N_NODES * 32 + 255) / 256, 256>>>(h);
        k_gemm1<<<GRID_G, 512, SMEM1>>>(l, b1 + (size_t)l * 256,
                bn1_g + (size_t)l * 256, bn1_b + (size_t)l * 256,
                bn1_m + (size_t)l * 256, bn1_v + (size_t)l * 256);
        k_gemm2<<<GRID_G, 512, SMEM2>>>(l, b2 + (size_t)l * 128,
                bno_g + (size_t)l * 128, bno_b + (size_t)l * 128,
                bno_m + (size_t)l * 128, bno_v + (size_t)l * 128,
                out, (l != LAYERS - 1) ? 1 : 0);
        h = out;
    }
}